// round 1
// baseline (speedup 1.0000x reference)
#include <cuda_runtime.h>

#define N_NODES 50000
#define N_EDGES 800000
#define HIDDEN 64
#define NODE_DIM 32
#define EDGE_DIM 16

// Accumulator row layout per node (80 floats): [0:16) = sum(ef), [16:80) = sum(h[src])
__device__ __align__(16) float g_acc[(size_t)N_NODES * 80];
__device__ __align__(16) float g_deg[N_NODES];

// ---------------------------------------------------------------------------
// Zero the accumulators (16MB + 200KB) with float4 stores.
// ---------------------------------------------------------------------------
__global__ void zero_kernel() {
    const int ACC4 = N_NODES * 80 / 4;   // 1,000,000
    const int DEG4 = N_NODES / 4;        // 12,500
    int i = blockIdx.x * blockDim.x + threadIdx.x;
    float4 z = make_float4(0.f, 0.f, 0.f, 0.f);
    if (i < ACC4) {
        reinterpret_cast<float4*>(g_acc)[i] = z;
    } else {
        int j = i - ACC4;
        if (j < DEG4) reinterpret_cast<float4*>(g_deg)[j] = z;
    }
}

// ---------------------------------------------------------------------------
// Edge scatter: task t = (edge e, chunk c), c in [0,20).
//   c in [0,16):  float4 chunk c of h[src[e]]  -> acc[dst][16 + 4c .. ]
//   c in [16,20): float4 chunk of ef[e]        -> acc[dst][4(c-16) .. ]
//   c == 0: deg[dst] += 1
// Vector reductions (red.global.add.v4.f32) — fire-and-forget into L2.
// ---------------------------------------------------------------------------
__device__ __forceinline__ void red_add_v4(float* p, float4 v) {
    asm volatile("red.global.add.v4.f32 [%0], {%1, %2, %3, %4};"
                 :: "l"(p), "f"(v.x), "f"(v.y), "f"(v.z), "f"(v.w)
                 : "memory");
}

__global__ void __launch_bounds__(256) edge_kernel(
    const float* __restrict__ h, const float* __restrict__ ef,
    const int* __restrict__ src, const int* __restrict__ dst)
{
    int t = blockIdx.x * 256 + threadIdx.x;
    if (t >= N_EDGES * 20) return;
    int e = t / 20;
    int c = t - e * 20;
    int d = dst[e];

    float4 v;
    float* p;
    if (c < 16) {
        int s = src[e];
        v = *reinterpret_cast<const float4*>(h + (size_t)s * HIDDEN + c * 4);
        p = g_acc + (size_t)d * 80 + 16 + c * 4;
    } else {
        int cc = c - 16;
        v = *reinterpret_cast<const float4*>(ef + (size_t)e * EDGE_DIM + cc * 4);
        p = g_acc + (size_t)d * 80 + cc * 4;
    }
    red_add_v4(p, v);
    if (c == 0) atomicAdd(g_deg + d, 1.0f);
}

// ---------------------------------------------------------------------------
// Node kernel: per 64-node tile, build Z^T[144][64] in smem,
//   Y = relu(Z @ W1^T)   (64x64, K=144)
//   O = Y @ W2^T         (64x64, K=64)
//   out[n] = deg[n] > 0 ? O[n] : h[n]
// 256 threads, 4x4 register microtiles, transposed smem operands (float4 LDS),
// rows padded to 68 floats (16B-aligned, reduces STS conflicts).
// ---------------------------------------------------------------------------
#define ROWP 68
#define ZT_OFF   0                      // 144*68 = 9792
#define W1T_OFF  9792                   // 144*68 = 9792
#define YT_OFF   19584                  // 64*68  = 4352
#define W2T_OFF  23936                  // 64*68  = 4352
#define SMEM_FLOATS 28288               // 113,152 bytes

__global__ void __launch_bounds__(256) node_kernel(
    const float* __restrict__ h, const float* __restrict__ nf,
    const float* __restrict__ W1, const float* __restrict__ W2,
    float* __restrict__ out)
{
    extern __shared__ float sm[];
    float* Zt  = sm + ZT_OFF;
    float* W1t = sm + W1T_OFF;
    float* Yt  = sm + YT_OFF;
    float* W2t = sm + W2T_OFF;

    const int tid  = threadIdx.x;
    const int base = blockIdx.x * 64;

    // Load W1 (64x144 row-major) transposed -> W1t[k][j]
    for (int idx = tid; idx < 64 * 144; idx += 256) {
        int j = idx / 144, k = idx - j * 144;
        W1t[k * ROWP + j] = W1[idx];
    }
    // Load W2 (64x64 row-major) transposed -> W2t[k][o]
    for (int idx = tid; idx < 64 * 64; idx += 256) {
        int o = idx >> 6, k = idx & 63;
        W2t[k * ROWP + o] = W2[idx];
    }
    // Build Z^T: z = [nf(32), deg*nf(32), sum_ef(16), sum_h(64)]
    for (int idx = tid; idx < 64 * 144; idx += 256) {
        int i = idx / 144, k = idx - i * 144;
        int n = base + i;
        float v = 0.f;
        if (n < N_NODES) {
            if (k < 32)       v = nf[n * 32 + k];
            else if (k < 64)  v = g_deg[n] * nf[n * 32 + (k - 32)];
            else if (k < 80)  v = g_acc[(size_t)n * 80 + (k - 64)];
            else              v = g_acc[(size_t)n * 80 + 16 + (k - 80)];
        }
        Zt[k * ROWP + i] = v;
    }
    __syncthreads();

    const int tx = tid & 15;   // node group: i in [tx*4, tx*4+4)
    const int ty = tid >> 4;   // out group:  j in [ty*4, ty*4+4)

    // ---- GEMM 1: Y = relu(Z @ W1^T), K = 144 ----
    float acc[4][4];
#pragma unroll
    for (int a = 0; a < 4; a++)
#pragma unroll
        for (int b = 0; b < 4; b++) acc[a][b] = 0.f;

#pragma unroll 4
    for (int k = 0; k < 144; k++) {
        float4 a4 = *reinterpret_cast<float4*>(&Zt[k * ROWP + tx * 4]);
        float4 b4 = *reinterpret_cast<float4*>(&W1t[k * ROWP + ty * 4]);
        float av[4] = {a4.x, a4.y, a4.z, a4.w};
        float bv[4] = {b4.x, b4.y, b4.z, b4.w};
#pragma unroll
        for (int ii = 0; ii < 4; ii++)
#pragma unroll
            for (int jj = 0; jj < 4; jj++)
                acc[ii][jj] += av[ii] * bv[jj];
    }

    // relu + store transposed: Yt[j][i]
#pragma unroll
    for (int jj = 0; jj < 4; jj++)
#pragma unroll
        for (int ii = 0; ii < 4; ii++)
            Yt[(ty * 4 + jj) * ROWP + tx * 4 + ii] = fmaxf(acc[ii][jj], 0.f);
    __syncthreads();

    // ---- GEMM 2: O = Y @ W2^T, K = 64 ----
    float acc2[4][4];
#pragma unroll
    for (int a = 0; a < 4; a++)
#pragma unroll
        for (int b = 0; b < 4; b++) acc2[a][b] = 0.f;

#pragma unroll 4
    for (int k = 0; k < 64; k++) {
        float4 a4 = *reinterpret_cast<float4*>(&Yt[k * ROWP + tx * 4]);
        float4 b4 = *reinterpret_cast<float4*>(&W2t[k * ROWP + ty * 4]);
        float av[4] = {a4.x, a4.y, a4.z, a4.w};
        float bv[4] = {b4.x, b4.y, b4.z, b4.w};
#pragma unroll
        for (int ii = 0; ii < 4; ii++)
#pragma unroll
            for (int jj = 0; jj < 4; jj++)
                acc2[ii][jj] += av[ii] * bv[jj];
    }

    // ---- Masked store: deg>0 ? new_h : h  (float4 per node-row segment) ----
#pragma unroll
    for (int ii = 0; ii < 4; ii++) {
        int n = base + tx * 4 + ii;
        if (n >= N_NODES) continue;
        bool has = (g_deg[n] > 0.f);
        float4 w;
        if (has) {
            w = make_float4(acc2[ii][0], acc2[ii][1], acc2[ii][2], acc2[ii][3]);
        } else {
            w = *reinterpret_cast<const float4*>(h + (size_t)n * HIDDEN + ty * 4);
        }
        *reinterpret_cast<float4*>(out + (size_t)n * HIDDEN + ty * 4) = w;
    }
}

// ---------------------------------------------------------------------------
extern "C" void kernel_launch(void* const* d_in, const int* in_sizes, int n_in,
                              void* d_out, int out_size)
{
    const float* h   = (const float*)d_in[0];
    const float* nf  = (const float*)d_in[1];
    const float* ef  = (const float*)d_in[2];
    const int*   src = (const int*)d_in[3];
    const int*   dst = (const int*)d_in[4];
    const float* W1  = (const float*)d_in[5];
    const float* W2  = (const float*)d_in[6];
    float*       out = (float*)d_out;

    const int zero_items = N_NODES * 80 / 4 + N_NODES / 4;   // 1,012,500
    zero_kernel<<<(zero_items + 255) / 256, 256>>>();

    const int tasks = N_EDGES * 20;                          // 16,000,000
    edge_kernel<<<(tasks + 255) / 256, 256>>>(h, ef, src, dst);

    cudaFuncSetAttribute(node_kernel, cudaFuncAttributeMaxDynamicSharedMemorySize,
                         SMEM_FLOATS * sizeof(float));
    node_kernel<<<(N_NODES + 63) / 64, 256, SMEM_FLOATS * sizeof(float)>>>(
        h, nf, W1, W2, out);
}

// round 2
// speedup vs baseline: 1.0049x; 1.0049x over previous
#include <cuda_runtime.h>

#define N_NODES 50000
#define N_EDGES 800000
#define HIDDEN 64
#define NODE_DIM 32
#define EDGE_DIM 16
#define CAP 96   // ELL capacity; deg ~ Poisson(16), max ~45. Overflow -> atomic fallback.

// Accumulator row per node (80 floats): [0:16) = sum(ef), [16:80) = sum(h[src])
__device__ __align__(16) float g_acc[(size_t)N_NODES * 80];
__device__ int   g_count[N_NODES];
__device__ __align__(8) int2 g_ell[(size_t)N_NODES * CAP];   // (src, edge_id)

__device__ __forceinline__ void red_add_v4(float* p, float4 v) {
    asm volatile("red.global.add.v4.f32 [%0], {%1, %2, %3, %4};"
                 :: "l"(p), "f"(v.x), "f"(v.y), "f"(v.z), "f"(v.w)
                 : "memory");
}

// ---------------------------------------------------------------------------
// Zero acc (16MB) and counts (200KB).
// ---------------------------------------------------------------------------
__global__ void zero_kernel() {
    const int ACC4 = N_NODES * 80 / 4;   // 1,000,000
    const int CNT4 = N_NODES / 4;        // 12,500
    int i = blockIdx.x * blockDim.x + threadIdx.x;
    if (i < ACC4) {
        reinterpret_cast<float4*>(g_acc)[i] = make_float4(0.f, 0.f, 0.f, 0.f);
    } else {
        int j = i - ACC4;
        if (j < CNT4) reinterpret_cast<int4*>(g_count)[j] = make_int4(0, 0, 0, 0);
    }
}

// ---------------------------------------------------------------------------
// Build ELL adjacency: one thread per edge claims a slot under its dst node.
// Overflow (never in practice): reduce directly into acc — always correct.
// ---------------------------------------------------------------------------
__global__ void __launch_bounds__(256) scatter_kernel(
    const float* __restrict__ h, const float* __restrict__ ef,
    const int* __restrict__ src, const int* __restrict__ dst)
{
    int e = blockIdx.x * 256 + threadIdx.x;
    if (e >= N_EDGES) return;
    int d = dst[e];
    int s = src[e];
    int pos = atomicAdd(&g_count[d], 1);
    if (pos < CAP) {
        g_ell[(size_t)d * CAP + pos] = make_int2(s, e);
    } else {
        // fallback: atomic reduce this edge's contribution directly
        float* row = g_acc + (size_t)d * 80;
        #pragma unroll
        for (int c = 0; c < 4; c++)
            red_add_v4(row + c * 4,
                       *reinterpret_cast<const float4*>(ef + (size_t)e * EDGE_DIM + c * 4));
        #pragma unroll
        for (int c = 0; c < 16; c++)
            red_add_v4(row + 16 + c * 4,
                       *reinterpret_cast<const float4*>(h + (size_t)s * HIDDEN + c * 4));
    }
}

// ---------------------------------------------------------------------------
// Warp-per-node gather: lanes 0-3 own ef float4 chunks, lanes 4-19 own h
// float4 chunks. Entries broadcast via shfl. One 80-float red per node.
// ---------------------------------------------------------------------------
__global__ void __launch_bounds__(256) gather_kernel(
    const float* __restrict__ h, const float* __restrict__ ef)
{
    int warp = (blockIdx.x * 256 + threadIdx.x) >> 5;   // 50,000 warps exactly
    int l = threadIdx.x & 31;
    if (warp >= N_NODES) return;
    int n = warp;
    int cnt = g_count[n];
    if (cnt > CAP) cnt = CAP;
    if (cnt == 0) return;

    float4 a = make_float4(0.f, 0.f, 0.f, 0.f);
    const size_t ebase = (size_t)n * CAP;

    for (int j0 = 0; j0 < cnt; j0 += 32) {
        int2 ent = make_int2(0, 0);
        if (j0 + l < cnt) ent = g_ell[ebase + j0 + l];
        int m = min(32, cnt - j0);
        for (int jj = 0; jj < m; jj++) {
            int s = __shfl_sync(0xffffffffu, ent.x, jj);
            int e = __shfl_sync(0xffffffffu, ent.y, jj);
            if (l < 20) {
                const float* p = (l < 4)
                    ? (ef + (size_t)e * EDGE_DIM + l * 4)
                    : (h  + (size_t)s * HIDDEN + (l - 4) * 4);
                float4 v = *reinterpret_cast<const float4*>(p);
                a.x += v.x; a.y += v.y; a.z += v.z; a.w += v.w;
            }
        }
    }
    if (l < 20)
        red_add_v4(g_acc + (size_t)n * 80 + l * 4, a);
}

// ---------------------------------------------------------------------------
// Node kernel: per 64-node tile, Z^T[144][64] in smem,
//   Y = relu(Z @ W1^T) (K=144), O = Y @ W2^T (K=64), masked by deg.
// ---------------------------------------------------------------------------
#define ROWP 68
#define ZT_OFF   0
#define W1T_OFF  9792
#define YT_OFF   19584
#define W2T_OFF  23936
#define SMEM_FLOATS 28288

__global__ void __launch_bounds__(256) node_kernel(
    const float* __restrict__ h, const float* __restrict__ nf,
    const float* __restrict__ W1, const float* __restrict__ W2,
    float* __restrict__ out)
{
    extern __shared__ float sm[];
    float* Zt  = sm + ZT_OFF;
    float* W1t = sm + W1T_OFF;
    float* Yt  = sm + YT_OFF;
    float* W2t = sm + W2T_OFF;

    const int tid  = threadIdx.x;
    const int base = blockIdx.x * 64;

    for (int idx = tid; idx < 64 * 144; idx += 256) {
        int j = idx / 144, k = idx - j * 144;
        W1t[k * ROWP + j] = W1[idx];
    }
    for (int idx = tid; idx < 64 * 64; idx += 256) {
        int o = idx >> 6, k = idx & 63;
        W2t[k * ROWP + o] = W2[idx];
    }
    for (int idx = tid; idx < 64 * 144; idx += 256) {
        int i = idx / 144, k = idx - i * 144;
        int n = base + i;
        float v = 0.f;
        if (n < N_NODES) {
            if (k < 32)       v = nf[n * 32 + k];
            else if (k < 64)  v = (float)g_count[n] * nf[n * 32 + (k - 32)];
            else if (k < 80)  v = g_acc[(size_t)n * 80 + (k - 64)];
            else              v = g_acc[(size_t)n * 80 + 16 + (k - 80)];
        }
        Zt[k * ROWP + i] = v;
    }
    __syncthreads();

    const int tx = tid & 15;
    const int ty = tid >> 4;

    float acc[4][4];
#pragma unroll
    for (int a = 0; a < 4; a++)
#pragma unroll
        for (int b = 0; b < 4; b++) acc[a][b] = 0.f;

#pragma unroll 4
    for (int k = 0; k < 144; k++) {
        float4 a4 = *reinterpret_cast<float4*>(&Zt[k * ROWP + tx * 4]);
        float4 b4 = *reinterpret_cast<float4*>(&W1t[k * ROWP + ty * 4]);
        float av[4] = {a4.x, a4.y, a4.z, a4.w};
        float bv[4] = {b4.x, b4.y, b4.z, b4.w};
#pragma unroll
        for (int ii = 0; ii < 4; ii++)
#pragma unroll
            for (int jj = 0; jj < 4; jj++)
                acc[ii][jj] += av[ii] * bv[jj];
    }

#pragma unroll
    for (int jj = 0; jj < 4; jj++)
#pragma unroll
        for (int ii = 0; ii < 4; ii++)
            Yt[(ty * 4 + jj) * ROWP + tx * 4 + ii] = fmaxf(acc[ii][jj], 0.f);
    __syncthreads();

    float acc2[4][4];
#pragma unroll
    for (int a = 0; a < 4; a++)
#pragma unroll
        for (int b = 0; b < 4; b++) acc2[a][b] = 0.f;

#pragma unroll 4
    for (int k = 0; k < 64; k++) {
        float4 a4 = *reinterpret_cast<float4*>(&Yt[k * ROWP + tx * 4]);
        float4 b4 = *reinterpret_cast<float4*>(&W2t[k * ROWP + ty * 4]);
        float av[4] = {a4.x, a4.y, a4.z, a4.w};
        float bv[4] = {b4.x, b4.y, b4.z, b4.w};
#pragma unroll
        for (int ii = 0; ii < 4; ii++)
#pragma unroll
            for (int jj = 0; jj < 4; jj++)
                acc2[ii][jj] += av[ii] * bv[jj];
    }

#pragma unroll
    for (int ii = 0; ii < 4; ii++) {
        int n = base + tx * 4 + ii;
        if (n >= N_NODES) continue;
        bool has = (g_count[n] > 0);
        float4 w;
        if (has) {
            w = make_float4(acc2[ii][0], acc2[ii][1], acc2[ii][2], acc2[ii][3]);
        } else {
            w = *reinterpret_cast<const float4*>(h + (size_t)n * HIDDEN + ty * 4);
        }
        *reinterpret_cast<float4*>(out + (size_t)n * HIDDEN + ty * 4) = w;
    }
}

// ---------------------------------------------------------------------------
extern "C" void kernel_launch(void* const* d_in, const int* in_sizes, int n_in,
                              void* d_out, int out_size)
{
    const float* h   = (const float*)d_in[0];
    const float* nf  = (const float*)d_in[1];
    const float* ef  = (const float*)d_in[2];
    const int*   src = (const int*)d_in[3];
    const int*   dst = (const int*)d_in[4];
    const float* W1  = (const float*)d_in[5];
    const float* W2  = (const float*)d_in[6];
    float*       out = (float*)d_out;

    const int zero_items = N_NODES * 80 / 4 + N_NODES / 4;
    zero_kernel<<<(zero_items + 255) / 256, 256>>>();

    scatter_kernel<<<(N_EDGES + 255) / 256, 256>>>(h, ef, src, dst);

    gather_kernel<<<(N_NODES * 32 + 255) / 256, 256>>>(h, ef);

    cudaFuncSetAttribute(node_kernel, cudaFuncAttributeMaxDynamicSharedMemorySize,
                         SMEM_FLOATS * sizeof(float));
    node_kernel<<<(N_NODES + 63) / 64, 256, SMEM_FLOATS * sizeof(float)>>>(
        h, nf, W1, W2, out);
}

// round 3
// speedup vs baseline: 1.3059x; 1.2996x over previous
#include <cuda_runtime.h>

#define N_NODES 50000
#define N_EDGES 800000
#define HIDDEN 64
#define NODE_DIM 32
#define EDGE_DIM 16
#define CAP 96
#define MPAD 50048            // 391 tiles * 128

// acc row per node (80 floats): [0:16)=sum(ef), [16:80)=sum(h[src])
__device__ __align__(16) float g_acc[(size_t)N_NODES * 80];
__device__ int   g_count[N_NODES];
__device__ int   g_ovf_cnt;
__device__ __align__(8) int2 g_ell[(size_t)N_NODES * CAP];   // (src, edge_id)
__device__ int3  g_ovf[N_EDGES];                             // (dst, src, edge)
__device__ __align__(16) float g_Y[(size_t)MPAD * 64];       // relu(Z@W1^T)

// ---------------------------------------------------------------------------
__global__ void zero_kernel() {
    int i = blockIdx.x * blockDim.x + threadIdx.x;
    const int CNT4 = N_NODES / 4;  // 12500
    if (i < CNT4) reinterpret_cast<int4*>(g_count)[i] = make_int4(0, 0, 0, 0);
    if (i == 0) g_ovf_cnt = 0;
}

// ---------------------------------------------------------------------------
__global__ void __launch_bounds__(256) scatter_kernel(
    const int* __restrict__ src, const int* __restrict__ dst)
{
    int e = blockIdx.x * 256 + threadIdx.x;
    if (e >= N_EDGES) return;
    int d = dst[e];
    int s = src[e];
    int pos = atomicAdd(&g_count[d], 1);
    if (pos < CAP) {
        g_ell[(size_t)d * CAP + pos] = make_int2(s, e);
    } else {
        int o = atomicAdd(&g_ovf_cnt, 1);
        g_ovf[o] = make_int3(d, s, e);
    }
}

// ---------------------------------------------------------------------------
// Warp-per-node gather. Lanes 0-3: ef chunks; lanes 4-19: h chunks.
// Plain STG at the end (no pre-zeroed acc needed).
// ---------------------------------------------------------------------------
__global__ void __launch_bounds__(256) gather_kernel(
    const float* __restrict__ h, const float* __restrict__ ef)
{
    int n = (blockIdx.x * 256 + threadIdx.x) >> 5;
    int l = threadIdx.x & 31;
    if (n >= N_NODES) return;
    int cnt_raw = g_count[n];
    if (cnt_raw == 0) return;
    int cnt = min(cnt_raw, CAP);

    float4 a = make_float4(0.f, 0.f, 0.f, 0.f);
    const size_t ebase = (size_t)n * CAP;

    for (int j0 = 0; j0 < cnt; j0 += 32) {
        int2 ent = make_int2(0, 0);
        if (j0 + l < cnt) ent = g_ell[ebase + j0 + l];
        int m = min(32, cnt - j0);
        for (int jj = 0; jj < m; jj++) {
            int s = __shfl_sync(0xffffffffu, ent.x, jj);
            int e = __shfl_sync(0xffffffffu, ent.y, jj);
            if (l < 20) {
                const float* p = (l < 4)
                    ? (ef + (size_t)e * EDGE_DIM + l * 4)
                    : (h  + (size_t)s * HIDDEN + (l - 4) * 4);
                float4 v = *reinterpret_cast<const float4*>(p);
                a.x += v.x; a.y += v.y; a.z += v.z; a.w += v.w;
            }
        }
    }
    // overflow path (practically never taken; exact when it is)
    if (cnt_raw > CAP) {
        int ovf = g_ovf_cnt;
        for (int i = 0; i < ovf; i++) {
            int3 t = g_ovf[i];
            if (t.x == n && l < 20) {
                const float* p = (l < 4)
                    ? (ef + (size_t)t.z * EDGE_DIM + l * 4)
                    : (h  + (size_t)t.y * HIDDEN + (l - 4) * 4);
                float4 v = *reinterpret_cast<const float4*>(p);
                a.x += v.x; a.y += v.y; a.z += v.z; a.w += v.w;
            }
        }
    }
    if (l < 20)
        *reinterpret_cast<float4*>(g_acc + (size_t)n * 80 + l * 4) = a;
}

// ---------------------------------------------------------------------------
// GEMM1: Y[m][n] = relu( sum_k Z[m][k] * W1[n][k] ), M=50048, N=64, K=144.
// Z assembled on the fly: [nf(32), deg*nf(32), acc_ef(16), acc_h(64)].
// Tile M=128, KC=16, 256 threads, 4x8 microtile.
// ---------------------------------------------------------------------------
#define AP 132
#define BP 68

__global__ void __launch_bounds__(256) gemm1_kernel(
    const float* __restrict__ nf, const float* __restrict__ W1)
{
    __shared__ float At[16 * AP];   // At[kk][m]
    __shared__ float Bt[16 * BP];   // Bt[kk][n]

    const int tid  = threadIdx.x;
    const int base = blockIdx.x * 128;
    const int tx = tid & 31;        // m group: rows tx*4 .. +3
    const int ty = tid >> 5;        // n group: cols ty*8 .. +7

    float acc[4][8];
#pragma unroll
    for (int i = 0; i < 4; i++)
#pragma unroll
        for (int j = 0; j < 8; j++) acc[i][j] = 0.f;

    const int m0 = (tid * 2) & 127;        // A-load rows (2 consecutive per thread)
    const int kgA = (tid * 2) >> 7;        // A-load k4 group (0..3)
    const int nB  = tid & 63;              // B-load row
    const int kgB = tid >> 6;              // B-load k4 group

    for (int kc = 0; kc < 9; kc++) {
        const int k0 = kc * 16;
        // ---- load A tile (transposed into At) ----
#pragma unroll
        for (int r = 0; r < 2; r++) {
            int m = m0 + r;
            int n = base + m;
            int gk = k0 + kgA * 4;
            float4 v = make_float4(0.f, 0.f, 0.f, 0.f);
            if (n < N_NODES) {
                if (gk < 32) {
                    v = *reinterpret_cast<const float4*>(nf + (size_t)n * 32 + gk);
                } else if (gk < 64) {
                    v = *reinterpret_cast<const float4*>(nf + (size_t)n * 32 + gk - 32);
                    float dg = (float)g_count[n];
                    v.x *= dg; v.y *= dg; v.z *= dg; v.w *= dg;
                } else if (gk < 80) {
                    v = *reinterpret_cast<const float4*>(g_acc + (size_t)n * 80 + (gk - 64));
                } else {
                    v = *reinterpret_cast<const float4*>(g_acc + (size_t)n * 80 + 16 + (gk - 80));
                }
            }
            At[(kgA * 4 + 0) * AP + m] = v.x;
            At[(kgA * 4 + 1) * AP + m] = v.y;
            At[(kgA * 4 + 2) * AP + m] = v.z;
            At[(kgA * 4 + 3) * AP + m] = v.w;
        }
        // ---- load B tile: W1[n][k0+kgB*4 ..] ----
        {
            float4 v = *reinterpret_cast<const float4*>(W1 + (size_t)nB * 144 + k0 + kgB * 4);
            Bt[(kgB * 4 + 0) * BP + nB] = v.x;
            Bt[(kgB * 4 + 1) * BP + nB] = v.y;
            Bt[(kgB * 4 + 2) * BP + nB] = v.z;
            Bt[(kgB * 4 + 3) * BP + nB] = v.w;
        }
        __syncthreads();

#pragma unroll
        for (int kk = 0; kk < 16; kk++) {
            float4 a4 = *reinterpret_cast<float4*>(&At[kk * AP + tx * 4]);
            float4 b0 = *reinterpret_cast<float4*>(&Bt[kk * BP + ty * 8]);
            float4 b1 = *reinterpret_cast<float4*>(&Bt[kk * BP + ty * 8 + 4]);
            float av[4] = {a4.x, a4.y, a4.z, a4.w};
            float bv[8] = {b0.x, b0.y, b0.z, b0.w, b1.x, b1.y, b1.z, b1.w};
#pragma unroll
            for (int i = 0; i < 4; i++)
#pragma unroll
                for (int j = 0; j < 8; j++)
                    acc[i][j] += av[i] * bv[j];
        }
        __syncthreads();
    }

    // relu + store Y (store pad rows too; they're zeros)
#pragma unroll
    for (int i = 0; i < 4; i++) {
        int m = base + tx * 4 + i;
        float4 w0 = make_float4(fmaxf(acc[i][0], 0.f), fmaxf(acc[i][1], 0.f),
                                fmaxf(acc[i][2], 0.f), fmaxf(acc[i][3], 0.f));
        float4 w1 = make_float4(fmaxf(acc[i][4], 0.f), fmaxf(acc[i][5], 0.f),
                                fmaxf(acc[i][6], 0.f), fmaxf(acc[i][7], 0.f));
        *reinterpret_cast<float4*>(g_Y + (size_t)m * 64 + ty * 8)     = w0;
        *reinterpret_cast<float4*>(g_Y + (size_t)m * 64 + ty * 8 + 4) = w1;
    }
}

// ---------------------------------------------------------------------------
// GEMM2: O = Y @ W2^T, K=64; epilogue masks with deg (out = h when deg==0).
// ---------------------------------------------------------------------------
__global__ void __launch_bounds__(256) gemm2_kernel(
    const float* __restrict__ h, const float* __restrict__ W2,
    float* __restrict__ out)
{
    __shared__ float At[16 * AP];
    __shared__ float Bt[16 * BP];

    const int tid  = threadIdx.x;
    const int base = blockIdx.x * 128;
    const int tx = tid & 31;
    const int ty = tid >> 5;

    float acc[4][8];
#pragma unroll
    for (int i = 0; i < 4; i++)
#pragma unroll
        for (int j = 0; j < 8; j++) acc[i][j] = 0.f;

    const int m0 = (tid * 2) & 127;
    const int kgA = (tid * 2) >> 7;
    const int nB  = tid & 63;
    const int kgB = tid >> 6;

    for (int kc = 0; kc < 4; kc++) {
        const int k0 = kc * 16;
#pragma unroll
        for (int r = 0; r < 2; r++) {
            int m = m0 + r;
            int gk = k0 + kgA * 4;
            float4 v = *reinterpret_cast<const float4*>(g_Y + (size_t)(base + m) * 64 + gk);
            At[(kgA * 4 + 0) * AP + m] = v.x;
            At[(kgA * 4 + 1) * AP + m] = v.y;
            At[(kgA * 4 + 2) * AP + m] = v.z;
            At[(kgA * 4 + 3) * AP + m] = v.w;
        }
        {
            float4 v = *reinterpret_cast<const float4*>(W2 + (size_t)nB * 64 + k0 + kgB * 4);
            Bt[(kgB * 4 + 0) * BP + nB] = v.x;
            Bt[(kgB * 4 + 1) * BP + nB] = v.y;
            Bt[(kgB * 4 + 2) * BP + nB] = v.z;
            Bt[(kgB * 4 + 3) * BP + nB] = v.w;
        }
        __syncthreads();

#pragma unroll
        for (int kk = 0; kk < 16; kk++) {
            float4 a4 = *reinterpret_cast<float4*>(&At[kk * AP + tx * 4]);
            float4 b0 = *reinterpret_cast<float4*>(&Bt[kk * BP + ty * 8]);
            float4 b1 = *reinterpret_cast<float4*>(&Bt[kk * BP + ty * 8 + 4]);
            float av[4] = {a4.x, a4.y, a4.z, a4.w};
            float bv[8] = {b0.x, b0.y, b0.z, b0.w, b1.x, b1.y, b1.z, b1.w};
#pragma unroll
            for (int i = 0; i < 4; i++)
#pragma unroll
                for (int j = 0; j < 8; j++)
                    acc[i][j] += av[i] * bv[j];
        }
        __syncthreads();
    }

#pragma unroll
    for (int i = 0; i < 4; i++) {
        int n = base + tx * 4 + i;
        if (n >= N_NODES) continue;
        float4 w0, w1;
        if (g_count[n] > 0) {
            w0 = make_float4(acc[i][0], acc[i][1], acc[i][2], acc[i][3]);
            w1 = make_float4(acc[i][4], acc[i][5], acc[i][6], acc[i][7]);
        } else {
            w0 = *reinterpret_cast<const float4*>(h + (size_t)n * HIDDEN + ty * 8);
            w1 = *reinterpret_cast<const float4*>(h + (size_t)n * HIDDEN + ty * 8 + 4);
        }
        *reinterpret_cast<float4*>(out + (size_t)n * HIDDEN + ty * 8)     = w0;
        *reinterpret_cast<float4*>(out + (size_t)n * HIDDEN + ty * 8 + 4) = w1;
    }
}

// ---------------------------------------------------------------------------
extern "C" void kernel_launch(void* const* d_in, const int* in_sizes, int n_in,
                              void* d_out, int out_size)
{
    const float* h   = (const float*)d_in[0];
    const float* nf  = (const float*)d_in[1];
    const float* ef  = (const float*)d_in[2];
    const int*   src = (const int*)d_in[3];
    const int*   dst = (const int*)d_in[4];
    const float* W1  = (const float*)d_in[5];
    const float* W2  = (const float*)d_in[6];
    float*       out = (float*)d_out;

    zero_kernel<<<(N_NODES / 4 + 255) / 256, 256>>>();
    scatter_kernel<<<(N_EDGES + 255) / 256, 256>>>(src, dst);
    gather_kernel<<<(N_NODES * 32 + 255) / 256, 256>>>(h, ef);

    const int mtiles = MPAD / 128;   // 391
    gemm1_kernel<<<mtiles, 256>>>(nf, W1);
    gemm2_kernel<<<mtiles, 256>>>(h, W2, out);
}

// round 5
// speedup vs baseline: 1.6689x; 1.2780x over previous
#include <cuda_runtime.h>

#define N_NODES 50000
#define N_EDGES 800000
#define HIDDEN 64
#define NODE_DIM 32
#define EDGE_DIM 16
#define CAP 96

// acc row per node (80 floats): [0:16)=sum(ef), [16:80)=sum(h[src])
__device__ __align__(16) float g_acc[(size_t)N_NODES * 80];
__device__ int   g_count[N_NODES];
__device__ int   g_ovf_cnt;
__device__ __align__(8) int2 g_ell[(size_t)N_NODES * CAP];
__device__ int3  g_ovf[N_EDGES];

typedef unsigned long long u64;

__device__ __forceinline__ void fma2(u64& d, u64 a, u64 b) {
    asm("fma.rn.f32x2 %0, %1, %2, %0;" : "+l"(d) : "l"(a), "l"(b));
}
__device__ __forceinline__ u64 rep2(float x) {
    u64 r;
    asm("mov.b64 %0, {%1, %1};" : "=l"(r) : "f"(x));
    return r;
}
__device__ __forceinline__ float2 unpack2(u64 v) {
    float2 p;
    asm("mov.b64 {%0, %1}, %2;" : "=f"(p.x), "=f"(p.y) : "l"(v));
    return p;
}

// ---------------------------------------------------------------------------
__global__ void zero_kernel() {
    int i = blockIdx.x * blockDim.x + threadIdx.x;
    const int CNT4 = N_NODES / 4;
    if (i < CNT4) reinterpret_cast<int4*>(g_count)[i] = make_int4(0, 0, 0, 0);
    if (i == 0) g_ovf_cnt = 0;
}

// ---------------------------------------------------------------------------
__global__ void __launch_bounds__(256) scatter_kernel(
    const int* __restrict__ src, const int* __restrict__ dst)
{
    int e = blockIdx.x * 256 + threadIdx.x;
    if (e >= N_EDGES) return;
    int d = dst[e];
    int s = src[e];
    int pos = atomicAdd(&g_count[d], 1);
    if (pos < CAP) {
        g_ell[(size_t)d * CAP + pos] = make_int2(s, e);
    } else {
        int o = atomicAdd(&g_ovf_cnt, 1);
        g_ovf[o] = make_int3(d, s, e);
    }
}

// ---------------------------------------------------------------------------
// Warp-per-node gather. ELL entries fetched with warp-uniform broadcast LDG
// (no shfl), unrolled x4 for MLP. Lanes 0-3: ef float4 chunks; 4-19: h chunks.
// ---------------------------------------------------------------------------
__device__ __forceinline__ void acc_edge(
    float4& a, int l, int s, int e,
    const float* __restrict__ h, const float* __restrict__ ef)
{
    if (l < 20) {
        const float* p = (l < 4)
            ? (ef + (size_t)e * EDGE_DIM + l * 4)
            : (h  + (size_t)s * HIDDEN + (l - 4) * 4);
        float4 v = *reinterpret_cast<const float4*>(p);
        a.x += v.x; a.y += v.y; a.z += v.z; a.w += v.w;
    }
}

__global__ void __launch_bounds__(256) gather_kernel(
    const float* __restrict__ h, const float* __restrict__ ef)
{
    int n = (blockIdx.x * 256 + threadIdx.x) >> 5;
    int l = threadIdx.x & 31;
    if (n >= N_NODES) return;
    int cnt_raw = g_count[n];
    if (cnt_raw == 0) return;
    int cnt = min(cnt_raw, CAP);

    float4 a = make_float4(0.f, 0.f, 0.f, 0.f);
    const int2* __restrict__ eb = g_ell + (size_t)n * CAP;

    int j = 0;
    for (; j + 4 <= cnt; j += 4) {
        int2 e0 = eb[j], e1 = eb[j + 1], e2 = eb[j + 2], e3 = eb[j + 3];
        acc_edge(a, l, e0.x, e0.y, h, ef);
        acc_edge(a, l, e1.x, e1.y, h, ef);
        acc_edge(a, l, e2.x, e2.y, h, ef);
        acc_edge(a, l, e3.x, e3.y, h, ef);
    }
    for (; j < cnt; j++) {
        int2 e = eb[j];
        acc_edge(a, l, e.x, e.y, h, ef);
    }
    if (cnt_raw > CAP) {     // exact fallback; practically never taken
        int ovf = g_ovf_cnt;
        for (int i = 0; i < ovf; i++) {
            int3 t = g_ovf[i];
            if (t.x == n) acc_edge(a, l, t.y, t.z, h, ef);
        }
    }
    if (l < 20)
        *reinterpret_cast<float4*>(g_acc + (size_t)n * 80 + l * 4) = a;
}

// ---------------------------------------------------------------------------
// Fused node kernel: per 128-node tile
//   phase 1: Y = relu(Z @ W1^T), K=144, Z assembled on the fly
//   phase 2: O = Y @ W2^T, K=64 (Y stays in smem)
// 128 threads, 4x16 microtile, packed f32x2 FMAs.
// Layouts (k-major, no padding needed — all LDS/STS are lane-stride-1 or
// warp-uniform):
//   At[16][128], Bt[16][64], W2t[64][64], Yt[64][128]
// ---------------------------------------------------------------------------
#define AT_OFF   0        // 16*128 = 2048
#define BT_OFF   2048     // 16*64  = 1024
#define W2T_OFF  3072     // 64*64  = 4096
#define YT_OFF   7168     // 64*128 = 8192
#define FUSED_SMEM_FLOATS 15360   // 61,440 bytes

__global__ void __launch_bounds__(128) fused_node_kernel(
    const float* __restrict__ h, const float* __restrict__ nf,
    const float* __restrict__ W1, const float* __restrict__ W2,
    float* __restrict__ out)
{
    extern __shared__ float sm[];
    float* At  = sm + AT_OFF;
    float* Bt  = sm + BT_OFF;
    float* W2t = sm + W2T_OFF;
    float* Yt  = sm + YT_OFF;

    const int tid  = threadIdx.x;
    const int tx   = tid & 31;        // lane: rows tx + 32*i
    const int ty   = tid >> 5;        // warp: cols ty*16 .. +15
    const int base = blockIdx.x * 128;

    // ---- one-time: W2 -> W2t[k][n] (covered by first kc barrier) ----
    {
        int n = tid & 63, half = tid >> 6;
        #pragma unroll
        for (int r = 0; r < 8; r++) {
            int kf4 = half + r * 2;                    // 0..15
            float4 v = *reinterpret_cast<const float4*>(W2 + (size_t)n * 64 + kf4 * 4);
            W2t[(kf4 * 4 + 0) * 64 + n] = v.x;
            W2t[(kf4 * 4 + 1) * 64 + n] = v.y;
            W2t[(kf4 * 4 + 2) * 64 + n] = v.z;
            W2t[(kf4 * 4 + 3) * 64 + n] = v.w;
        }
    }

    u64 accP[4][8];
#pragma unroll
    for (int i = 0; i < 4; i++)
#pragma unroll
        for (int j = 0; j < 8; j++) accP[i][j] = 0ull;

    const int nrow = base + tid;           // A-loader row (one per thread)
    const bool valid = (nrow < N_NODES);
    const float degf = valid ? (float)g_count[nrow] : 0.f;

    // ======================= phase 1: K = 144 =======================
    for (int kc = 0; kc < 9; kc++) {
        const int k0 = kc * 16;
        if (kc > 0) __syncthreads();       // protect At/Bt reuse

        // A tile: thread loads 4 float4 of Z[nrow][k0..k0+15]
        #pragma unroll
        for (int kg = 0; kg < 4; kg++) {
            int gk = k0 + kg * 4;
            float4 v = make_float4(0.f, 0.f, 0.f, 0.f);
            if (valid) {
                if (gk < 32) {
                    v = *reinterpret_cast<const float4*>(nf + (size_t)nrow * 32 + gk);
                } else if (gk < 64) {
                    v = *reinterpret_cast<const float4*>(nf + (size_t)nrow * 32 + gk - 32);
                    v.x *= degf; v.y *= degf; v.z *= degf; v.w *= degf;
                } else if (gk < 80) {
                    v = *reinterpret_cast<const float4*>(g_acc + (size_t)nrow * 80 + (gk - 64));
                } else {
                    v = *reinterpret_cast<const float4*>(g_acc + (size_t)nrow * 80 + 16 + (gk - 80));
                }
            }
            At[(kg * 4 + 0) * 128 + tid] = v.x;
            At[(kg * 4 + 1) * 128 + tid] = v.y;
            At[(kg * 4 + 2) * 128 + tid] = v.z;
            At[(kg * 4 + 3) * 128 + tid] = v.w;
        }
        // B tile: W1[n][k0..k0+15], 2 float4 per thread
        {
            int n = tid & 63, kp = tid >> 6;
            #pragma unroll
            for (int rr = 0; rr < 2; rr++) {
                int kg = kp * 2 + rr;
                float4 v = *reinterpret_cast<const float4*>(W1 + (size_t)n * 144 + k0 + kg * 4);
                Bt[(kg * 4 + 0) * 64 + n] = v.x;
                Bt[(kg * 4 + 1) * 64 + n] = v.y;
                Bt[(kg * 4 + 2) * 64 + n] = v.z;
                Bt[(kg * 4 + 3) * 64 + n] = v.w;
            }
        }
        __syncthreads();

        #pragma unroll
        for (int kk = 0; kk < 16; kk++) {
            float a[4];
            #pragma unroll
            for (int i = 0; i < 4; i++) a[i] = At[kk * 128 + tx + 32 * i];
            u64 b[8];
            #pragma unroll
            for (int j2 = 0; j2 < 8; j2++)
                b[j2] = *reinterpret_cast<const u64*>(&Bt[kk * 64 + ty * 16 + j2 * 2]);
            #pragma unroll
            for (int i = 0; i < 4; i++) {
                u64 ar = rep2(a[i]);
                #pragma unroll
                for (int j2 = 0; j2 < 8; j2++) fma2(accP[i][j2], ar, b[j2]);
            }
        }
    }

    // relu -> Yt[k][m], reset accumulators
    __syncthreads();
#pragma unroll
    for (int i = 0; i < 4; i++)
#pragma unroll
        for (int j2 = 0; j2 < 8; j2++) {
            float2 p = unpack2(accP[i][j2]);
            Yt[(ty * 16 + j2 * 2 + 0) * 128 + tx + 32 * i] = fmaxf(p.x, 0.f);
            Yt[(ty * 16 + j2 * 2 + 1) * 128 + tx + 32 * i] = fmaxf(p.y, 0.f);
            accP[i][j2] = 0ull;
        }
    __syncthreads();

    // ======================= phase 2: K = 64 =======================
#pragma unroll 8
    for (int kk = 0; kk < 64; kk++) {
        float a[4];
        #pragma unroll
        for (int i = 0; i < 4; i++) a[i] = Yt[kk * 128 + tx + 32 * i];
        u64 b[8];
        #pragma unroll
        for (int j2 = 0; j2 < 8; j2++)
            b[j2] = *reinterpret_cast<const u64*>(&W2t[kk * 64 + ty * 16 + j2 * 2]);
        #pragma unroll
        for (int i = 0; i < 4; i++) {
            u64 ar = rep2(a[i]);
            #pragma unroll
            for (int j2 = 0; j2 < 8; j2++) fma2(accP[i][j2], ar, b[j2]);
        }
    }

    // ---- epilogue: mask by deg, write out ----
#pragma unroll
    for (int i = 0; i < 4; i++) {
        int n = base + tx + 32 * i;
        if (n >= N_NODES) continue;
        bool has = (g_count[n] > 0);
        #pragma unroll
        for (int q = 0; q < 2; q++) {     // two float4 per 16-col strip half
            float4 w;
            if (has) {
                float2 p0 = unpack2(accP[i][q * 2 + 0]);
                float2 p1 = unpack2(accP[i][q * 2 + 1]);
                w = make_float4(p0.x, p0.y, p1.x, p1.y);
            } else {
                w = *reinterpret_cast<const float4*>(h + (size_t)n * HIDDEN + ty * 16 + q * 4);
            }
            *reinterpret_cast<float4*>(out + (size_t)n * HIDDEN + ty * 16 + q * 4) = w;
        }
        // second half of the 16 cols
        #pragma unroll
        for (int q = 0; q < 2; q++) {
            float4 w;
            if (has) {
                float2 p0 = unpack2(accP[i][4 + q * 2 + 0]);
                float2 p1 = unpack2(accP[i][4 + q * 2 + 1]);
                w = make_float4(p0.x, p0.y, p1.x, p1.y);
            } else {
                w = *reinterpret_cast<const float4*>(h + (size_t)n * HIDDEN + ty * 16 + 8 + q * 4);
            }
            *reinterpret_cast<float4*>(out + (size_t)n * HIDDEN + ty * 16 + 8 + q * 4) = w;
        }
    }
}

// ---------------------------------------------------------------------------
extern "C" void kernel_launch(void* const* d_in, const int* in_sizes, int n_in,
                              void* d_out, int out_size)
{
    const float* h   = (const float*)d_in[0];
    const float* nf  = (const float*)d_in[1];
    const float* ef  = (const float*)d_in[2];
    const int*   src = (const int*)d_in[3];
    const int*   dst = (const int*)d_in[4];
    const float* W1  = (const float*)d_in[5];
    const float* W2  = (const float*)d_in[6];
    float*       out = (float*)d_out;

    zero_kernel<<<(N_NODES / 4 + 255) / 256, 256>>>();
    scatter_kernel<<<(N_EDGES + 255) / 256, 256>>>(src, dst);
    gather_kernel<<<(N_NODES * 32 + 255) / 256, 256>>>(h, ef);

    cudaFuncSetAttribute(fused_node_kernel,
                         cudaFuncAttributeMaxDynamicSharedMemorySize,
                         FUSED_SMEM_FLOATS * sizeof(float));
    const int blocks = (N_NODES + 127) / 128;   // 391
    fused_node_kernel<<<blocks, 128, FUSED_SMEM_FLOATS * sizeof(float)>>>(
        h, nf, W1, W2, out);
}